// round 6
// baseline (speedup 1.0000x reference)
#include <cuda_runtime.h>
#include <cuda_bf16.h>

#define DD 96
#define NSEG 50
#define NT 301
#define BATCH 256
#define OUTW 4656          // 96 + 96*95/2
#define TILES_PB 8
#define GRID (BATCH * NSEG / TILES_PB)   // 1600

// ---- Youla decomposition of the 6x6 antisymmetric tridiagonal form ----
#define S1d 0.4338837391175581204757683328483
#define S2d 0.7818314824680298087084445266741
#define S3d 0.9749279121818236070181316829939
#define C1d 0.9009688679024191262361023195074
#define C2d 0.6234898018587335305250048840042
#define C3d 0.2225209339563144042889025644968
// A[i,j] = sum_k P_k[i] Q_k[j] - Q_k[i] P_k[j]
__device__ __constant__ float PA[3][3] = {
    { (float)(-(C1d/1.75)*S2d), (float)( (C1d/1.75)*S3d), (float)(-(C1d/1.75)*S1d) },
    { (float)(-(C2d/1.75)*S3d), (float)(-(C2d/1.75)*S1d), (float)( (C2d/1.75)*S2d) },
    { (float)(-(C3d/1.75)*S1d), (float)(-(C3d/1.75)*S2d), (float)(-(C3d/1.75)*S3d) },
};
__device__ __constant__ float QB[3][3] = {
    { (float)( S1d), (float)(-S3d), (float)( S2d) },
    { (float)( S2d), (float)(-S1d), (float)(-S3d) },
    { (float)( S3d), (float)( S2d), (float)( S1d) },
};

typedef unsigned long long u64;

__device__ __forceinline__ u64 fma2(u64 a, u64 b, u64 c) {
    u64 d; asm("fma.rn.f32x2 %0, %1, %2, %3;" : "=l"(d) : "l"(a), "l"(b), "l"(c)); return d;
}
__device__ __forceinline__ u64 mul2(u64 a, u64 b) {
    u64 d; asm("mul.rn.f32x2 %0, %1, %2;" : "=l"(d) : "l"(a), "l"(b)); return d;
}
__device__ __forceinline__ void unpack2(u64 v, float& lo, float& hi) {
    asm("mov.b64 {%0, %1}, %2;" : "=f"(lo), "=f"(hi) : "l"(v));
}

// double-buffered staging:
//  j-side (scalar pairs, LDS.64 of 2 consecutive j):   Qsc, NPsc
//  row-side (pre-duplicated {v,v}, LDS.64 broadcast):  Pdup, Qdup
struct SBuf {
    float  Qsc[3][DD];
    float  NPsc[3][DD];
    float2 Pdup[3][DD];
    float2 Qdup[3][DD];
};

// One 8-row group (this half-warp: rows i0..i0+3, i0 = 8g + 4*half) over
// j-tiles jt = JTF..2. jt == JTF is the boundary tile (masked).
// Row classes by r = i mod 4: r=0,1 -> odd triangular base (2x STG.32);
// r=2,3 -> even base (STG.64 straight from the packed accumulator).
template<int JTF>
__device__ __forceinline__ void do_group(int g, int half, int jl,
                                         const SBuf* __restrict__ sb,
                                         float* __restrict__ o)
{
    const int i0 = 8 * g + 4 * half;

    float* rb[4];
    #pragma unroll
    for (int r = 0; r < 4; r++) {
        const int i = i0 + r;
        rb[r] = o + DD + i * 95 - ((i * (i - 1)) >> 1) - i - 1 + 2 * jl;
    }

    #pragma unroll
    for (int jt = JTF; jt < 3; jt++) {
        u64 acc[4];
        #pragma unroll
        for (int k = 0; k < 3; k++) {
            const u64 qp  = *(const u64*)&sb->Qsc[k][32 * jt + 2 * jl];
            const u64 npp = *(const u64*)&sb->NPsc[k][32 * jt + 2 * jl];
            #pragma unroll
            for (int r = 0; r < 4; r++) {
                const u64 pd = *(const u64*)&sb->Pdup[k][i0 + r];  // broadcast LDS.64
                const u64 qd = *(const u64*)&sb->Qdup[k][i0 + r];  // broadcast LDS.64
                if (k == 0) acc[r] = mul2(pd, qp);
                else        acc[r] = fma2(pd, qp, acc[r]);
                acc[r] = fma2(qd, npp, acc[r]);
            }
        }

        const int off = 32 * jt;
        if (jt == JTF) {
            const int j0 = 32 * JTF + 2 * jl;
            #pragma unroll
            for (int r = 0; r < 4; r++) {
                const int i = i0 + r;
                float lo, hi; unpack2(acc[r], lo, hi);
                if (r < 2) {
                    if (j0     > i) rb[r][off]     = lo;
                    if (j0 + 1 > i) rb[r][off + 1] = hi;
                } else {
                    if (j0 > i)       *(u64*)&rb[r][off] = acc[r];
                    else if (j0 == i) rb[r][off + 1] = hi;
                }
            }
        } else {
            #pragma unroll
            for (int r = 0; r < 4; r++) {
                if (r < 2) {
                    float lo, hi; unpack2(acc[r], lo, hi);
                    rb[r][off]     = lo;
                    rb[r][off + 1] = hi;
                } else {
                    *(u64*)&rb[r][off] = acc[r];
                }
            }
        }
    }
}

__global__ __launch_bounds__(256, 4)
void logsig_kernel(const float* __restrict__ inp, float* __restrict__ out)
{
    __shared__ __align__(16) SBuf sb[2];

    const int tid  = threadIdx.x;
    const int warp = tid >> 5;
    const int lane = tid & 31;
    const int half = lane >> 4;
    const int jl   = lane & 15;

    const int bs0 = blockIdx.x * TILES_PB;

    // prefetch tile 0 inputs
    float pf[7];
    if (tid < DD) {
        const int b = bs0 / NSEG, s = bs0 - b * NSEG;
        const float* __restrict__ p = inp + ((size_t)b * NT + 6 * s) * DD + tid;
        #pragma unroll
        for (int t = 0; t < 7; t++) pf[t] = p[t * DD];
    }

    int buf = 0;
    for (int it = 0; it < TILES_PB; it++) {
        const int bs = bs0 + it;
        float* __restrict__ o = out + (size_t)bs * OUTW;

        // stage P/Q from prefetched registers
        if (tid < DD) {
            const float p0 = pf[0];
            const float y1 = pf[1] - p0, y2 = pf[2] - p0, y3 = pf[3] - p0;
            const float y4 = pf[4] - p0, y5 = pf[5] - p0, y6 = pf[6] - p0;
            o[tid] = y6;  // level-1 term
            #pragma unroll
            for (int k = 0; k < 3; k++) {
                float Pk = fmaf(PA[k][0], y2, fmaf(PA[k][1], y4, PA[k][2] * y6));
                float Qk = fmaf(QB[k][0], y1, fmaf(QB[k][1], y3, QB[k][2] * y5));
                sb[buf].Qsc[k][tid]  = Qk;
                sb[buf].NPsc[k][tid] = -Pk;
                sb[buf].Pdup[k][tid] = make_float2(Pk, Pk);
                sb[buf].Qdup[k][tid] = make_float2(Qk, Qk);
            }
        }
        __syncthreads();

        // prefetch next tile (latency hidden behind compute)
        if (it + 1 < TILES_PB && tid < DD) {
            const int bs2 = bs + 1;
            const int b2 = bs2 / NSEG, s2 = bs2 - b2 * NSEG;
            const float* __restrict__ p2 = inp + ((size_t)b2 * NT + 6 * s2) * DD + tid;
            #pragma unroll
            for (int t = 0; t < 7; t++) pf[t] = p2[t * DD];
        }

        // compute + store: 12 groups of 8 rows, 24 warp-tiles, 3 per warp
        const SBuf* sp = &sb[buf];
        if (warp < 4) {
            do_group<0>(warp, half, jl, sp, o);          // groups 0-3: jt 0,1,2
        } else {
            do_group<1>(warp, half, jl, sp, o);          // groups 4-7: jt 1,2
            do_group<2>(warp + 4, half, jl, sp, o);      // groups 8-11: jt 2
        }

        buf ^= 1;
        // one barrier per iteration suffices with double buffering
    }
}

extern "C" void kernel_launch(void* const* d_in, const int* in_sizes, int n_in,
                              void* d_out, int out_size)
{
    const float* inp = (const float*)d_in[0];
    float* out = (float*)d_out;
    logsig_kernel<<<GRID, 256>>>(inp, out);
}

// round 7
// speedup vs baseline: 1.3758x; 1.3758x over previous
#include <cuda_runtime.h>
#include <cuda_bf16.h>

#define DD 96
#define NSEG 50
#define NT 301
#define BATCH 256
#define OUTW 4656          // 96 + 96*95/2
#define TOTSEG (BATCH * NSEG)   // 12800
#define GRIDP 444          // 148 SMs x 3 resident blocks, persistent

// ---- Youla decomposition of the 6x6 antisymmetric tridiagonal form ----
#define S1d 0.4338837391175581204757683328483
#define S2d 0.7818314824680298087084445266741
#define S3d 0.9749279121818236070181316829939
#define C1d 0.9009688679024191262361023195074
#define C2d 0.6234898018587335305250048840042
#define C3d 0.2225209339563144042889025644968
// A[i,j] = sum_k P_k[i] Q_k[j] - Q_k[i] P_k[j]
__device__ __constant__ float PA[3][3] = {
    { (float)(-(C1d/1.75)*S2d), (float)( (C1d/1.75)*S3d), (float)(-(C1d/1.75)*S1d) },
    { (float)(-(C2d/1.75)*S3d), (float)(-(C2d/1.75)*S1d), (float)( (C2d/1.75)*S2d) },
    { (float)(-(C3d/1.75)*S1d), (float)(-(C3d/1.75)*S2d), (float)(-(C3d/1.75)*S3d) },
};
__device__ __constant__ float QB[3][3] = {
    { (float)( S1d), (float)(-S3d), (float)( S2d) },
    { (float)( S2d), (float)(-S1d), (float)(-S3d) },
    { (float)( S3d), (float)( S2d), (float)( S1d) },
};

typedef unsigned long long u64;

__device__ __forceinline__ u64 pack2f(float lo, float hi) {
    u64 r; asm("mov.b64 %0, {%1, %2};" : "=l"(r) : "f"(lo), "f"(hi)); return r;
}
__device__ __forceinline__ u64 fma2(u64 a, u64 b, u64 c) {
    u64 d; asm("fma.rn.f32x2 %0, %1, %2, %3;" : "=l"(d) : "l"(a), "l"(b), "l"(c)); return d;
}
__device__ __forceinline__ u64 mul2(u64 a, u64 b) {
    u64 d; asm("mul.rn.f32x2 %0, %1, %2;" : "=l"(d) : "l"(a), "l"(b)); return d;
}
__device__ __forceinline__ void unpack2(u64 v, float& lo, float& hi) {
    asm("mov.b64 {%0, %1}, %2;" : "=f"(lo), "=f"(hi) : "l"(v));
}

// double-buffered staging (R5 layout: scalar arrays; row side read as LDS.32
// into registers, j side read as LDS.64 pairs)
struct SBuf {
    float Ps[3][DD];
    float Qs[3][DD];
    float NPs[3][DD];
};

// One 8-row group (this half-warp: rows i0..i0+3, i0 = 8g + 4*half) over
// j-tiles jt = JTF..2. jt == JTF is the boundary tile (masked).
// Row classes by r = i mod 4: r=0,1 -> odd triangular base (2x STG.32);
// r=2,3 -> even base (STG.64 straight from the packed accumulator).
template<int JTF>
__device__ __forceinline__ void do_group(int g, int half, int jl,
                                         const SBuf* __restrict__ sb,
                                         float* __restrict__ o)
{
    const int i0 = 8 * g + 4 * half;

    // row-side scalars -> register-resident packs (reused across all tiles)
    float Pr[3][4], Qr[3][4];
    #pragma unroll
    for (int k = 0; k < 3; k++)
        #pragma unroll
        for (int r = 0; r < 4; r++) {
            Pr[k][r] = sb->Ps[k][i0 + r];
            Qr[k][r] = sb->Qs[k][i0 + r];
        }

    float* rb[4];
    #pragma unroll
    for (int r = 0; r < 4; r++) {
        const int i = i0 + r;
        rb[r] = o + DD + i * 95 - ((i * (i - 1)) >> 1) - i - 1 + 2 * jl;
    }

    #pragma unroll
    for (int jt = JTF; jt < 3; jt++) {
        u64 acc[4];
        #pragma unroll
        for (int k = 0; k < 3; k++) {
            const u64 qp  = *(const u64*)&sb->Qs[k][32 * jt + 2 * jl];
            const u64 npp = *(const u64*)&sb->NPs[k][32 * jt + 2 * jl];
            #pragma unroll
            for (int r = 0; r < 4; r++) {
                const u64 pd = pack2f(Pr[k][r], Pr[k][r]);
                const u64 qd = pack2f(Qr[k][r], Qr[k][r]);
                if (k == 0) acc[r] = mul2(pd, qp);
                else        acc[r] = fma2(pd, qp, acc[r]);
                acc[r] = fma2(qd, npp, acc[r]);
            }
        }

        const int off = 32 * jt;
        if (jt == JTF) {
            const int j0 = 32 * JTF + 2 * jl;
            #pragma unroll
            for (int r = 0; r < 4; r++) {
                const int i = i0 + r;
                float lo, hi; unpack2(acc[r], lo, hi);
                if (r < 2) {
                    if (j0     > i) rb[r][off]     = lo;
                    if (j0 + 1 > i) rb[r][off + 1] = hi;
                } else {
                    if (j0 > i)       *(u64*)&rb[r][off] = acc[r];
                    else if (j0 == i) rb[r][off + 1] = hi;
                }
            }
        } else {
            #pragma unroll
            for (int r = 0; r < 4; r++) {
                if (r < 2) {
                    float lo, hi; unpack2(acc[r], lo, hi);
                    rb[r][off]     = lo;
                    rb[r][off + 1] = hi;
                } else {
                    *(u64*)&rb[r][off] = acc[r];
                }
            }
        }
    }
}

__global__ __launch_bounds__(256, 3)
void logsig_kernel(const float* __restrict__ inp, float* __restrict__ out)
{
    __shared__ __align__(16) SBuf sb[2];

    const int tid  = threadIdx.x;
    const int warp = tid >> 5;
    const int lane = tid & 31;
    const int half = lane >> 4;
    const int jl   = lane & 15;

    // prefetch first segment
    float pf[7];
    if (tid < DD) {
        const int bs = blockIdx.x;
        const int b = bs / NSEG, s = bs - b * NSEG;
        const float* __restrict__ p = inp + ((size_t)b * NT + 6 * s) * DD + tid;
        #pragma unroll
        for (int t = 0; t < 7; t++) pf[t] = p[t * DD];
    }

    int buf = 0;
    for (int bs = blockIdx.x; bs < TOTSEG; bs += GRIDP) {
        float* __restrict__ o = out + (size_t)bs * OUTW;

        // stage P/Q from prefetched registers
        if (tid < DD) {
            const float p0 = pf[0];
            const float y1 = pf[1] - p0, y2 = pf[2] - p0, y3 = pf[3] - p0;
            const float y4 = pf[4] - p0, y5 = pf[5] - p0, y6 = pf[6] - p0;
            o[tid] = y6;  // level-1 term
            #pragma unroll
            for (int k = 0; k < 3; k++) {
                float Pk = fmaf(PA[k][0], y2, fmaf(PA[k][1], y4, PA[k][2] * y6));
                float Qk = fmaf(QB[k][0], y1, fmaf(QB[k][1], y3, QB[k][2] * y5));
                sb[buf].Ps[k][tid]  = Pk;
                sb[buf].Qs[k][tid]  = Qk;
                sb[buf].NPs[k][tid] = -Pk;
            }
        }
        __syncthreads();

        // prefetch the block's next segment (latency hidden behind compute)
        const int bs2 = bs + GRIDP;
        if (bs2 < TOTSEG && tid < DD) {
            const int b2 = bs2 / NSEG, s2 = bs2 - b2 * NSEG;
            const float* __restrict__ p2 = inp + ((size_t)b2 * NT + 6 * s2) * DD + tid;
            #pragma unroll
            for (int t = 0; t < 7; t++) pf[t] = p2[t * DD];
        }

        // compute + store: 12 groups of 8 rows, 24 warp-tiles, 3 per warp
        const SBuf* sp = &sb[buf];
        if (warp < 4) {
            do_group<0>(warp, half, jl, sp, o);          // groups 0-3: jt 0,1,2
        } else {
            do_group<1>(warp, half, jl, sp, o);          // groups 4-7: jt 1,2
            do_group<2>(warp + 4, half, jl, sp, o);      // groups 8-11: jt 2
        }

        buf ^= 1;
        // one barrier per iteration suffices with double buffering:
        // compute(t) reads buf; next write of buf is stage(t+2), which is
        // separated from compute(t) by the iter-(t+1) barrier.
    }
}

extern "C" void kernel_launch(void* const* d_in, const int* in_sizes, int n_in,
                              void* d_out, int out_size)
{
    const float* inp = (const float*)d_in[0];
    float* out = (float*)d_out;
    logsig_kernel<<<GRIDP, 256>>>(inp, out);
}